// round 6
// baseline (speedup 1.0000x reference)
#include <cuda_runtime.h>
#include <cuda_bf16.h>
#include <cstdint>

// Shapes (fixed by the problem)
#define B_  64
#define T_  512
#define D_  768
#define L_  31            // NUM_LABELS
#define NTOK (B_*T_)      // 32768
#define IDX_EOS 29
#define IDX_BOS 30

// Scratch (static __device__, no allocation)
__device__ float g_outs[NTOK * L_];   // out_s (post bias + mask adjust)
__device__ float g_eos [NTOK * L_];   // exp(out_s)

// ---------------------------------------------------------------------------
// Kernel 1: out_s = input @ state_w^T + state_b  (+ mask EOS adjust), eos=exp
// 64 tokens x 32 labels per block, 128 threads, 4x4 register tile, K-chunk 16.
// ---------------------------------------------------------------------------
__global__ __launch_bounds__(128) void gemm_kernel(
    const float* __restrict__ input,
    const float* __restrict__ state_w,
    const float* __restrict__ state_b,
    const float* __restrict__ mask)
{
    __shared__ float sA[16][64];   // [k][token]
    __shared__ float sB[16][32];   // [k][label]

    const int tid = threadIdx.x;
    const int tx  = tid & 15;      // token group (4 tokens)
    const int ty  = tid >> 4;      // label group (4 labels), 0..7
    const int tokbase = blockIdx.x * 64;
    const float* inp = input + (size_t)tokbase * D_;

    float acc[4][4];
#pragma unroll
    for (int m = 0; m < 4; m++)
#pragma unroll
        for (int n = 0; n < 4; n++) acc[m][n] = 0.f;

    for (int k0 = 0; k0 < D_; k0 += 16) {
        // load input tile: 64 rows x 16 k  (each thread: 2 float4)
        {
            const int row = tid >> 1;
#pragma unroll
            for (int q = 0; q < 2; q++) {
                const int c4 = (tid & 1) * 2 + q;
                float4 v = *(const float4*)&inp[(size_t)row * D_ + k0 + c4 * 4];
                sA[c4*4+0][row] = v.x; sA[c4*4+1][row] = v.y;
                sA[c4*4+2][row] = v.z; sA[c4*4+3][row] = v.w;
            }
        }
        // load weight tile: 31 rows x 16 k  (124 threads x float4), pad row 31
        if (tid < 124) {
            const int l = tid >> 2, c4 = tid & 3;
            float4 v = *(const float4*)&state_w[(size_t)l * D_ + k0 + c4 * 4];
            sB[c4*4+0][l] = v.x; sB[c4*4+1][l] = v.y;
            sB[c4*4+2][l] = v.z; sB[c4*4+3][l] = v.w;
        } else {
            const int q = tid - 124;
#pragma unroll
            for (int u = 0; u < 4; u++) sB[q*4+u][31] = 0.f;
        }
        __syncthreads();

#pragma unroll
        for (int kk = 0; kk < 16; kk++) {
            float4 a = *(const float4*)&sA[kk][tx * 4];
            float4 b = *(const float4*)&sB[kk][ty * 4];
            acc[0][0] = fmaf(a.x, b.x, acc[0][0]); acc[0][1] = fmaf(a.x, b.y, acc[0][1]);
            acc[0][2] = fmaf(a.x, b.z, acc[0][2]); acc[0][3] = fmaf(a.x, b.w, acc[0][3]);
            acc[1][0] = fmaf(a.y, b.x, acc[1][0]); acc[1][1] = fmaf(a.y, b.y, acc[1][1]);
            acc[1][2] = fmaf(a.y, b.z, acc[1][2]); acc[1][3] = fmaf(a.y, b.w, acc[1][3]);
            acc[2][0] = fmaf(a.z, b.x, acc[2][0]); acc[2][1] = fmaf(a.z, b.y, acc[2][1]);
            acc[2][2] = fmaf(a.z, b.z, acc[2][2]); acc[2][3] = fmaf(a.z, b.w, acc[2][3]);
            acc[3][0] = fmaf(a.w, b.x, acc[3][0]); acc[3][1] = fmaf(a.w, b.y, acc[3][1]);
            acc[3][2] = fmaf(a.w, b.z, acc[3][2]); acc[3][3] = fmaf(a.w, b.w, acc[3][3]);
        }
        __syncthreads();
    }

    // epilogue
#pragma unroll
    for (int m = 0; m < 4; m++) {
        const int g = tokbase + tx * 4 + m;
        const float mk = mask[g];
#pragma unroll
        for (int n = 0; n < 4; n++) {
            const int j = ty * 4 + n;
            if (j < L_) {
                float v = acc[m][n] + __ldg(&state_b[j]);
                if (j == IDX_EOS) v += (mk == 0.f) ? 20000.f : 0.f;
                g_outs[(size_t)g * L_ + j] = v;
                g_eos [(size_t)g * L_ + j] = __expf(v);
            }
        }
    }
}

// ---------------------------------------------------------------------------
// Kernel 2: energy[b,t,i,j] = trans[i,j] + out_s[b,t,j]   (126 MB write)
// 992 threads (961 active), 4 tokens per block.
// ---------------------------------------------------------------------------
__global__ __launch_bounds__(992) void energy_kernel(
    const float* __restrict__ trans,
    float* __restrict__ energy)
{
    const int r = threadIdx.x;            // 0..991
    if (r >= L_ * L_) return;
    const int j = r % L_;                 // constant-mod, cheap
    const float tr = __ldg(&trans[r]);
    const int tokbase = blockIdx.x * 4;
#pragma unroll
    for (int k = 0; k < 4; k++) {
        const int tok = tokbase + k;
        energy[(size_t)tok * (L_ * L_) + r] = tr + __ldg(&g_outs[(size_t)tok * L_ + j]);
    }
}

// ---------------------------------------------------------------------------
// Kernel 3: linear-space forward scan + target energy + loss. One warp per b.
// Lane j holds p[j] (= exp(part[j] - logC)), W column exp(trans[:,j]) in regs.
// ---------------------------------------------------------------------------
__device__ __forceinline__ float stepf(float p, const float (&w)[L_], float e)
{
    float a0 = 0.f, a1 = 0.f, a2 = 0.f, a3 = 0.f;
#pragma unroll
    for (int i = 0; i < L_; i += 4) {
        a0 = fmaf(w[i],   __shfl_sync(0xffffffffu, p, i),   a0);
        if (i + 1 < L_) a1 = fmaf(w[i+1], __shfl_sync(0xffffffffu, p, i+1), a1);
        if (i + 2 < L_) a2 = fmaf(w[i+2], __shfl_sync(0xffffffffu, p, i+2), a2);
        if (i + 3 < L_) a3 = fmaf(w[i+3], __shfl_sync(0xffffffffu, p, i+3), a3);
    }
    return ((a0 + a1) + (a2 + a3)) * e;
}

__global__ __launch_bounds__(32) void scan_kernel(
    const float* __restrict__ trans,
    const int* __restrict__ target32,   // raw target buffer viewed as int32
    float* __restrict__ loss)
{
    const int b = blockIdx.x;
    const int j = threadIdx.x;            // 0..31
    const bool act = (j < L_);
    const float* eb = g_eos + (size_t)b * T_ * L_;

    // --- dtype detection: int64 target (LE) has zero high words at odd int32
    //     positions; labels are 0..28 so a real int32 buffer has all values in
    //     0..28 and 64 consecutive zero labels has probability 29^-64 ~ 0.
    bool is64 = true;
#pragma unroll
    for (int q = 0; q < 64; q++) is64 &= (__ldg(&target32[2 * q + 1]) == 0);
    const int tstride = is64 ? 2 : 1;

    float w[L_];
#pragma unroll
    for (int i = 0; i < L_; i++)
        w[i] = act ? __expf(__ldg(&trans[i * L_ + j])) : 0.f;

    // part0 = trans[BOS,:] + out_s[:,0,:]  ->  p = exp(trans[BOS,j]) * eos[0,j]
    float p = act ? __expf(__ldg(&trans[IDX_BOS * L_ + j])) * __ldg(&eb[j]) : 0.f;
    float logC = 0.f;

    float e0[8], e1[8];
    // steps t=1..7 (prologue), then 63 chunks of 8 (t=8..511)
#pragma unroll
    for (int u = 0; u < 7; u++) e0[u] = act ? eb[(1 + u) * L_ + j] : 0.f;
#pragma unroll
    for (int u = 0; u < 8; u++) e1[u] = act ? eb[(8 + u) * L_ + j] : 0.f;

#pragma unroll
    for (int u = 0; u < 7; u++) p = stepf(p, w, e0[u]);
    {
        float m = __uint_as_float(__reduce_max_sync(0xffffffffu, __float_as_uint(p)));
        p *= __fdividef(1.f, m);
        logC += __logf(m);
    }

    for (int o = 1; o < 64; o++) {
#pragma unroll
        for (int u = 0; u < 8; u++) e0[u] = e1[u];
        if (o < 63) {
            const int tn = (o + 1) * 8;
#pragma unroll
            for (int u = 0; u < 8; u++)
                e1[u] = act ? eb[(tn + u) * L_ + j] : 0.f;
        }
#pragma unroll
        for (int u = 0; u < 8; u++) p = stepf(p, w, e0[u]);
        float m = __uint_as_float(__reduce_max_sync(0xffffffffu, __float_as_uint(p)));
        p *= __fdividef(1.f, m);
        logC += __logf(m);
    }

    // target energy: sum_t trans[prev,tgt] + out_s[b,t,tgt]
    const size_t tb = (size_t)b * T_;
    float ts = 0.f;
    for (int t = j; t < T_; t += 32) {
        int tgt  = __ldg(&target32[(tb + t) * tstride]);
        int prev = (t == 0) ? IDX_BOS : __ldg(&target32[(tb + t - 1) * tstride]);
        tgt  = min(max(tgt,  0), L_ - 1);   // defensive clamp
        prev = min(max(prev, 0), L_ - 1);
        ts += __ldg(&trans[prev * L_ + tgt]) + __ldg(&g_outs[(tb + t) * L_ + tgt]);
    }
#pragma unroll
    for (int s = 16; s; s >>= 1) ts += __shfl_xor_sync(0xffffffffu, ts, s);

    // loss = logC + log( sum_j exp(trans[j,EOS]) * p[j] ) - tgt_energy
    float v = act ? __expf(__ldg(&trans[j * L_ + IDX_EOS])) * p : 0.f;
#pragma unroll
    for (int s = 16; s; s >>= 1) v += __shfl_xor_sync(0xffffffffu, v, s);

    if (j == 0) loss[b] = logC + __logf(v) - ts;
}

// ---------------------------------------------------------------------------
extern "C" void kernel_launch(void* const* d_in, const int* in_sizes, int n_in,
                              void* d_out, int out_size)
{
    const float* input   = (const float*)d_in[0];
    const int*   target  = (const int*)d_in[1];   // int32 or int64 (auto-detected)
    const float* mask    = (const float*)d_in[2];
    const float* state_w = (const float*)d_in[3];
    const float* state_b = (const float*)d_in[4];
    const float* trans   = (const float*)d_in[5];

    float* out    = (float*)d_out;
    float* loss   = out;            // 64 floats
    float* energy = out + B_;       // B*T*31*31 floats

    gemm_kernel<<<NTOK / 64, 128>>>(input, state_w, state_b, mask);
    energy_kernel<<<NTOK / 4, 992>>>(trans, energy);
    scan_kernel<<<B_, 32>>>(trans, target, loss);
}

// round 7
// speedup vs baseline: 1.1231x; 1.1231x over previous
#include <cuda_runtime.h>
#include <cuda_bf16.h>
#include <cstdint>

// Shapes (fixed by the problem)
#define B_  64
#define T_  512
#define D_  768
#define L_  31            // NUM_LABELS
#define LL_ 961           // L_*L_
#define NTOK (B_*T_)      // 32768
#define IDX_EOS 29
#define IDX_BOS 30

typedef unsigned long long ull;

// Scratch (static __device__, no allocation)
__device__ float g_outs[NTOK * L_];   // out_s (post bias + mask adjust)
__device__ float g_eos [NTOK * L_];   // exp(out_s)

// packed f32x2 FMA: {acc.lo,acc.hi} += {a.lo*b.lo, a.hi*b.hi}
__device__ __forceinline__ void ffma2(ull& acc, ull a, ull b) {
    asm("fma.rn.f32x2 %0, %1, %2, %0;" : "+l"(acc) : "l"(a), "l"(b));
}

// ---------------------------------------------------------------------------
// Kernel 1: out_s = input @ state_w^T + b (+mask EOS), eos = exp(out_s)
// Block: 128 threads, tile 128 tokens x 32 labels. Thread tile 8x4.
// K-packed FFMA2: acc holds {sum over even k, sum over odd k}.
// smem rows padded to 20 floats -> conflict-free LDS.128.
// ---------------------------------------------------------------------------
__global__ __launch_bounds__(128) void gemm_kernel(
    const float* __restrict__ input,
    const float* __restrict__ state_w,
    const float* __restrict__ state_b,
    const float* __restrict__ mask)
{
    __shared__ __align__(16) float sA[2][128 * 20];   // [token][16k + pad4]
    __shared__ __align__(16) float sB[2][32 * 20];    // [label][16k + pad4]

    const int tid = threadIdx.x;
    const int tx  = tid & 15;          // token group
    const int ty  = tid >> 4;          // label group 0..7
    const int tokbase = blockIdx.x * 128;
    const float* gA = input + (size_t)tokbase * D_;

    ull acc[8][4];
#pragma unroll
    for (int m = 0; m < 8; m++)
#pragma unroll
        for (int n = 0; n < 4; n++) acc[m][n] = 0ull;

    // prefetch regs
    float4 pa[4]; float4 pb = make_float4(0.f, 0.f, 0.f, 0.f);
    const int la_tok = tid >> 2;       // for B loads: label row (tid<124)
    const int la_c4  = tid & 3;

    // ---- load chunk 0 ----
#pragma unroll
    for (int i = 0; i < 4; i++) {
        const int idx = i * 128 + tid;
        pa[i] = *(const float4*)&gA[(size_t)(idx >> 2) * D_ + (idx & 3) * 4];
    }
    if (tid < 124) pb = *(const float4*)&state_w[(size_t)la_tok * D_ + la_c4 * 4];

    // store chunk 0
    {
#pragma unroll
        for (int i = 0; i < 4; i++) {
            const int idx = i * 128 + tid;
            *(float4*)&sA[0][(idx >> 2) * 20 + (idx & 3) * 4] = pa[i];
        }
        if (tid < 124) *(float4*)&sB[0][la_tok * 20 + la_c4 * 4] = pb;
        else           *(float4*)&sB[0][31 * 20 + (tid - 124) * 4] = make_float4(0,0,0,0);
    }
    __syncthreads();

    int buf = 0;
    for (int c = 0; c < 48; c++) {
        // prefetch next chunk into regs
        if (c < 47) {
            const int k0n = (c + 1) * 16;
#pragma unroll
            for (int i = 0; i < 4; i++) {
                const int idx = i * 128 + tid;
                pa[i] = *(const float4*)&gA[(size_t)(idx >> 2) * D_ + k0n + (idx & 3) * 4];
            }
            if (tid < 124)
                pb = *(const float4*)&state_w[(size_t)la_tok * D_ + k0n + la_c4 * 4];
        }

        // compute current chunk
        const float* A = &sA[buf][0];
        const float* Bp = &sB[buf][0];
#pragma unroll
        for (int kk4 = 0; kk4 < 4; kk4++) {
            ull b0[4], b1[4];
#pragma unroll
            for (int n = 0; n < 4; n++) {
                ulonglong2 t = *(const ulonglong2*)&Bp[(ty * 4 + n) * 20 + kk4 * 4];
                b0[n] = t.x; b1[n] = t.y;
            }
#pragma unroll
            for (int m = 0; m < 8; m++) {
                ulonglong2 t = *(const ulonglong2*)&A[(m * 16 + tx) * 20 + kk4 * 4];
#pragma unroll
                for (int n = 0; n < 4; n++) {
                    ffma2(acc[m][n], t.x, b0[n]);
                    ffma2(acc[m][n], t.y, b1[n]);
                }
            }
        }

        // store prefetched chunk into other buffer
        if (c < 47) {
            const int ob = buf ^ 1;
#pragma unroll
            for (int i = 0; i < 4; i++) {
                const int idx = i * 128 + tid;
                *(float4*)&sA[ob][(idx >> 2) * 20 + (idx & 3) * 4] = pa[i];
            }
            if (tid < 124) *(float4*)&sB[ob][la_tok * 20 + la_c4 * 4] = pb;
            else           *(float4*)&sB[ob][31 * 20 + (tid - 124) * 4] = make_float4(0,0,0,0);
        }
        __syncthreads();
        buf ^= 1;
    }

    // epilogue
#pragma unroll
    for (int m = 0; m < 8; m++) {
        const int g = tokbase + m * 16 + tx;
        const float mk = mask[g];
#pragma unroll
        for (int n = 0; n < 4; n++) {
            const int j = ty * 4 + n;
            if (j < L_) {
                const float lo = __uint_as_float((unsigned)(acc[m][n] & 0xffffffffull));
                const float hi = __uint_as_float((unsigned)(acc[m][n] >> 32));
                float v = lo + hi + __ldg(&state_b[j]);
                if (j == IDX_EOS) v += (mk == 0.f) ? 20000.f : 0.f;
                g_outs[(size_t)g * L_ + j] = v;
                g_eos [(size_t)g * L_ + j] = __expf(v);
            }
        }
    }
}

// ---------------------------------------------------------------------------
// Scan step: p_new[j] = e[j] * sum_i w[i][j] * p[i]   (lane j holds p[j])
// ---------------------------------------------------------------------------
__device__ __forceinline__ float stepf(float p, const float (&w)[L_], float e)
{
    float a0 = 0.f, a1 = 0.f, a2 = 0.f, a3 = 0.f;
#pragma unroll
    for (int i = 0; i < L_; i += 4) {
        a0 = fmaf(w[i],   __shfl_sync(0xffffffffu, p, i),   a0);
        if (i + 1 < L_) a1 = fmaf(w[i+1], __shfl_sync(0xffffffffu, p, i+1), a1);
        if (i + 2 < L_) a2 = fmaf(w[i+2], __shfl_sync(0xffffffffu, p, i+2), a2);
        if (i + 3 < L_) a3 = fmaf(w[i+3], __shfl_sync(0xffffffffu, p, i+3), a3);
    }
    return ((a0 + a1) + (a2 + a3)) * e;
}

__device__ __forceinline__ void scan_body(
    int b, int j,
    const float* __restrict__ trans,
    const int* __restrict__ target32,
    float* __restrict__ loss)
{
    const bool act = (j < L_);
    const float* eb = g_eos + (size_t)b * T_ * L_;

    // dtype detection: int64 target (LE) has zero high words at odd positions
    bool is64 = true;
#pragma unroll
    for (int q = 0; q < 64; q++) is64 &= (__ldg(&target32[2 * q + 1]) == 0);
    const int tstride = is64 ? 2 : 1;

    float w[L_];
#pragma unroll
    for (int i = 0; i < L_; i++)
        w[i] = act ? __expf(__ldg(&trans[i * L_ + j])) : 0.f;

    float p = act ? __expf(__ldg(&trans[IDX_BOS * L_ + j])) * __ldg(&eb[j]) : 0.f;
    float logC = 0.f;

    float e0[8], e1[8];
#pragma unroll
    for (int u = 0; u < 7; u++) e0[u] = act ? eb[(1 + u) * L_ + j] : 0.f;
#pragma unroll
    for (int u = 0; u < 8; u++) e1[u] = act ? eb[(8 + u) * L_ + j] : 0.f;

#pragma unroll
    for (int u = 0; u < 7; u++) p = stepf(p, w, e0[u]);
    {
        float m = __uint_as_float(__reduce_max_sync(0xffffffffu, __float_as_uint(p)));
        p *= __fdividef(1.f, m);
        logC += __logf(m);
    }

    for (int o = 1; o < 64; o++) {
#pragma unroll
        for (int u = 0; u < 8; u++) e0[u] = e1[u];
        if (o < 63) {
            const int tn = (o + 1) * 8;
#pragma unroll
            for (int u = 0; u < 8; u++)
                e1[u] = act ? eb[(tn + u) * L_ + j] : 0.f;
        }
#pragma unroll
        for (int u = 0; u < 8; u++) p = stepf(p, w, e0[u]);
        float m = __uint_as_float(__reduce_max_sync(0xffffffffu, __float_as_uint(p)));
        p *= __fdividef(1.f, m);
        logC += __logf(m);
    }

    // target energy
    const size_t tb = (size_t)b * T_;
    float ts = 0.f;
    for (int t = j; t < T_; t += 32) {
        int tgt  = __ldg(&target32[(tb + t) * tstride]);
        int prev = (t == 0) ? IDX_BOS : __ldg(&target32[(tb + t - 1) * tstride]);
        tgt  = min(max(tgt,  0), L_ - 1);
        prev = min(max(prev, 0), L_ - 1);
        ts += __ldg(&trans[prev * L_ + tgt]) + __ldg(&g_outs[(tb + t) * L_ + tgt]);
    }
#pragma unroll
    for (int s = 16; s; s >>= 1) ts += __shfl_xor_sync(0xffffffffu, ts, s);

    float v = act ? __expf(__ldg(&trans[j * L_ + IDX_EOS])) * p : 0.f;
#pragma unroll
    for (int s = 16; s; s >>= 1) v += __shfl_xor_sync(0xffffffffu, v, s);

    if (j == 0) loss[b] = logC + __logf(v) - ts;
}

// ---------------------------------------------------------------------------
// Fused kernel: blocks [0,64) = per-batch scan (warp 0 only);
// blocks [64, gridDim) = float4 grid-stride energy write.
// energy[tok*961 + r] = trans[r] + out_s[tok*31 + r%31]
// ---------------------------------------------------------------------------
#define SCANB 64
#define ENERB 960
#define NV4   (NTOK * LL_ / 4)   // 7,872,512 float4s

__global__ __launch_bounds__(256) void fused_kernel(
    const float* __restrict__ trans,
    const int* __restrict__ target32,
    float* __restrict__ loss,
    float* __restrict__ energy)
{
    if (blockIdx.x < SCANB) {
        if (threadIdx.x < 32)
            scan_body(blockIdx.x, threadIdx.x, trans, target32, loss);
        return;
    }

    unsigned v = (blockIdx.x - SCANB) * 256u + threadIdx.x;
    const unsigned stride = ENERB * 256u;
    for (; v < (unsigned)NV4; v += stride) {
        const unsigned f = v * 4u;
        float4 o;
        {
            unsigned ff = f;
            unsigned tok = ff / (unsigned)LL_;
            unsigned r   = ff - tok * (unsigned)LL_;
            unsigned j   = r % (unsigned)L_;
            o.x = __ldg(&trans[r]) + __ldg(&g_outs[tok * L_ + j]);
        }
        {
            unsigned ff = f + 1u;
            unsigned tok = ff / (unsigned)LL_;
            unsigned r   = ff - tok * (unsigned)LL_;
            unsigned j   = r % (unsigned)L_;
            o.y = __ldg(&trans[r]) + __ldg(&g_outs[tok * L_ + j]);
        }
        {
            unsigned ff = f + 2u;
            unsigned tok = ff / (unsigned)LL_;
            unsigned r   = ff - tok * (unsigned)LL_;
            unsigned j   = r % (unsigned)L_;
            o.z = __ldg(&trans[r]) + __ldg(&g_outs[tok * L_ + j]);
        }
        {
            unsigned ff = f + 3u;
            unsigned tok = ff / (unsigned)LL_;
            unsigned r   = ff - tok * (unsigned)LL_;
            unsigned j   = r % (unsigned)L_;
            o.w = __ldg(&trans[r]) + __ldg(&g_outs[tok * L_ + j]);
        }
        ((float4*)energy)[v] = o;
    }
}

// ---------------------------------------------------------------------------
extern "C" void kernel_launch(void* const* d_in, const int* in_sizes, int n_in,
                              void* d_out, int out_size)
{
    const float* input   = (const float*)d_in[0];
    const int*   target  = (const int*)d_in[1];   // int32 or int64 (auto-detected)
    const float* mask    = (const float*)d_in[2];
    const float* state_w = (const float*)d_in[3];
    const float* state_b = (const float*)d_in[4];
    const float* trans   = (const float*)d_in[5];

    float* out    = (float*)d_out;
    float* loss   = out;            // 64 floats
    float* energy = out + B_;       // B*T*31*31 floats (16B-aligned: offset 256B)

    gemm_kernel<<<NTOK / 128, 128>>>(input, state_w, state_b, mask);
    fused_kernel<<<SCANB + ENERB, 256>>>(trans, target, loss, energy);
}

// round 8
// speedup vs baseline: 1.4351x; 1.2779x over previous
#include <cuda_runtime.h>
#include <cuda_bf16.h>
#include <cstdint>

// Shapes (fixed by the problem)
#define B_  64
#define T_  512
#define D_  768
#define L_  31            // NUM_LABELS
#define LL_ 961           // L_*L_
#define NTOK (B_*T_)      // 32768
#define IDX_EOS 29
#define IDX_BOS 30

typedef unsigned long long ull;

// Scratch (static __device__, no allocation)
__device__ float g_outs[NTOK * L_];   // out_s (post bias + mask adjust)
__device__ float g_eos [NTOK * L_];   // exp(out_s)

// packed f32x2 FMA: {acc.lo,acc.hi} += {a.lo*b.lo, a.hi*b.hi}
__device__ __forceinline__ void ffma2(ull& acc, ull a, ull b) {
    asm("fma.rn.f32x2 %0, %1, %2, %0;" : "+l"(acc) : "l"(a), "l"(b));
}

// ---------------------------------------------------------------------------
// Kernel 1: out_s = input @ state_w^T + b (+mask EOS), eos = exp(out_s)
// (unchanged from R7 — known good at ~82us)
// ---------------------------------------------------------------------------
__global__ __launch_bounds__(128) void gemm_kernel(
    const float* __restrict__ input,
    const float* __restrict__ state_w,
    const float* __restrict__ state_b,
    const float* __restrict__ mask)
{
    __shared__ __align__(16) float sA[2][128 * 20];   // [token][16k + pad4]
    __shared__ __align__(16) float sB[2][32 * 20];    // [label][16k + pad4]

    const int tid = threadIdx.x;
    const int tx  = tid & 15;          // token group
    const int ty  = tid >> 4;          // label group 0..7
    const int tokbase = blockIdx.x * 128;
    const float* gA = input + (size_t)tokbase * D_;

    ull acc[8][4];
#pragma unroll
    for (int m = 0; m < 8; m++)
#pragma unroll
        for (int n = 0; n < 4; n++) acc[m][n] = 0ull;

    float4 pa[4]; float4 pb = make_float4(0.f, 0.f, 0.f, 0.f);
    const int la_tok = tid >> 2;
    const int la_c4  = tid & 3;

#pragma unroll
    for (int i = 0; i < 4; i++) {
        const int idx = i * 128 + tid;
        pa[i] = *(const float4*)&gA[(size_t)(idx >> 2) * D_ + (idx & 3) * 4];
    }
    if (tid < 124) pb = *(const float4*)&state_w[(size_t)la_tok * D_ + la_c4 * 4];

    {
#pragma unroll
        for (int i = 0; i < 4; i++) {
            const int idx = i * 128 + tid;
            *(float4*)&sA[0][(idx >> 2) * 20 + (idx & 3) * 4] = pa[i];
        }
        if (tid < 124) *(float4*)&sB[0][la_tok * 20 + la_c4 * 4] = pb;
        else           *(float4*)&sB[0][31 * 20 + (tid - 124) * 4] = make_float4(0,0,0,0);
    }
    __syncthreads();

    int buf = 0;
    for (int c = 0; c < 48; c++) {
        if (c < 47) {
            const int k0n = (c + 1) * 16;
#pragma unroll
            for (int i = 0; i < 4; i++) {
                const int idx = i * 128 + tid;
                pa[i] = *(const float4*)&gA[(size_t)(idx >> 2) * D_ + k0n + (idx & 3) * 4];
            }
            if (tid < 124)
                pb = *(const float4*)&state_w[(size_t)la_tok * D_ + k0n + la_c4 * 4];
        }

        const float* A = &sA[buf][0];
        const float* Bp = &sB[buf][0];
#pragma unroll
        for (int kk4 = 0; kk4 < 4; kk4++) {
            ull b0[4], b1[4];
#pragma unroll
            for (int n = 0; n < 4; n++) {
                ulonglong2 t = *(const ulonglong2*)&Bp[(ty * 4 + n) * 20 + kk4 * 4];
                b0[n] = t.x; b1[n] = t.y;
            }
#pragma unroll
            for (int m = 0; m < 8; m++) {
                ulonglong2 t = *(const ulonglong2*)&A[(m * 16 + tx) * 20 + kk4 * 4];
#pragma unroll
                for (int n = 0; n < 4; n++) {
                    ffma2(acc[m][n], t.x, b0[n]);
                    ffma2(acc[m][n], t.y, b1[n]);
                }
            }
        }

        if (c < 47) {
            const int ob = buf ^ 1;
#pragma unroll
            for (int i = 0; i < 4; i++) {
                const int idx = i * 128 + tid;
                *(float4*)&sA[ob][(idx >> 2) * 20 + (idx & 3) * 4] = pa[i];
            }
            if (tid < 124) *(float4*)&sB[ob][la_tok * 20 + la_c4 * 4] = pb;
            else           *(float4*)&sB[ob][31 * 20 + (tid - 124) * 4] = make_float4(0,0,0,0);
        }
        __syncthreads();
        buf ^= 1;
    }

#pragma unroll
    for (int m = 0; m < 8; m++) {
        const int g = tokbase + m * 16 + tx;
        const float mk = mask[g];
#pragma unroll
        for (int n = 0; n < 4; n++) {
            const int j = ty * 4 + n;
            if (j < L_) {
                const float lo = __uint_as_float((unsigned)(acc[m][n] & 0xffffffffull));
                const float hi = __uint_as_float((unsigned)(acc[m][n] >> 32));
                float v = lo + hi + __ldg(&state_b[j]);
                if (j == IDX_EOS) v += (mk == 0.f) ? 20000.f : 0.f;
                g_outs[(size_t)g * L_ + j] = v;
                g_eos [(size_t)g * L_ + j] = __expf(v);
            }
        }
    }
}

// ---------------------------------------------------------------------------
// Scan: linear-space forward recursion, sparse W via smem pair-gathers.
// Lane j holds p[j]. Per step: STS p -> syncwarp -> 8x LDS.64 -> 16-FMA tree.
// W = exp(trans): column j nonzeros live in row pairs:
//   heavy cols (j%4==0, j%4==3, j==29): pairs {2,6,10,14,18,22,26,28}
//   light cols (j%4==1 or 2, j<28):    single pair 4*(j>>2)
// Zero entries come out naturally as exp(-10000)=0; row/col BOS is all-zero.
// ---------------------------------------------------------------------------
__device__ __forceinline__ float step2(float p, const float (&w)[16],
                                       const int (&offs)[8], float* sp,
                                       int buf, int j, float e)
{
    sp[buf + j] = p;
    __syncwarp();
    const float* s = sp + buf;
    float2 x0 = *(const float2*)&s[offs[0]];
    float2 x1 = *(const float2*)&s[offs[1]];
    float2 x2 = *(const float2*)&s[offs[2]];
    float2 x3 = *(const float2*)&s[offs[3]];
    float2 x4 = *(const float2*)&s[offs[4]];
    float2 x5 = *(const float2*)&s[offs[5]];
    float2 x6 = *(const float2*)&s[offs[6]];
    float2 x7 = *(const float2*)&s[offs[7]];
    float t0 = fmaf(w[0],  x0.x, w[1]  * x0.y);
    float t1 = fmaf(w[2],  x1.x, w[3]  * x1.y);
    float t2 = fmaf(w[4],  x2.x, w[5]  * x2.y);
    float t3 = fmaf(w[6],  x3.x, w[7]  * x3.y);
    float t4 = fmaf(w[8],  x4.x, w[9]  * x4.y);
    float t5 = fmaf(w[10], x5.x, w[11] * x5.y);
    float t6 = fmaf(w[12], x6.x, w[13] * x6.y);
    float t7 = fmaf(w[14], x7.x, w[15] * x7.y);
    return (((t0 + t1) + (t2 + t3)) + ((t4 + t5) + (t6 + t7))) * e;
}

__device__ __forceinline__ void scan_body(
    int b, int j,
    const float* __restrict__ trans,
    const int* __restrict__ target32,
    float* __restrict__ loss,
    float* sp)                       // 64-float smem buffer (double)
{
    const bool act = (j < L_);
    const float* eb = g_eos + (size_t)b * T_ * L_;

    // dtype detection: int64 target (LE) has zero high words at odd positions
    bool is64 = true;
#pragma unroll
    for (int q = 0; q < 64; q++) is64 &= (__ldg(&target32[2 * q + 1]) == 0);
    const int tstride = is64 ? 2 : 1;

    // per-lane gather offsets (all even -> aligned LDS.64)
    const bool light = (j < 28) && (((j & 3) == 1) || ((j & 3) == 2));
    int offs[8];
    offs[0] = light ? ((j >> 2) << 2) : 2;
#pragma unroll
    for (int k = 1; k < 7; k++) offs[k] = 4 * k + 2;   // 6,10,14,18,22,26
    offs[7] = 28;

    // 16 weights: exp(trans[row, j]) for rows offs[k], offs[k]+1
    float w[16];
#pragma unroll
    for (int k = 0; k < 8; k++) {
        w[2*k]   = act ? __expf(__ldg(&trans[offs[k] * L_ + j]))       : 0.f;
        w[2*k+1] = act ? __expf(__ldg(&trans[(offs[k]+1) * L_ + j]))   : 0.f;
    }

    float p = act ? __expf(__ldg(&trans[IDX_BOS * L_ + j])) * __ldg(&eb[j]) : 0.f;
    float logC = 0.f;
    int buf = 0;

    float e0[8], e1[8];
#pragma unroll
    for (int u = 0; u < 7; u++) e0[u] = act ? eb[(1 + u) * L_ + j] : 0.f;
#pragma unroll
    for (int u = 0; u < 8; u++) e1[u] = act ? eb[(8 + u) * L_ + j] : 0.f;

#pragma unroll
    for (int u = 0; u < 7; u++) { p = step2(p, w, offs, sp, buf, j, e0[u]); buf ^= 32; }
    {
        float m = __uint_as_float(__reduce_max_sync(0xffffffffu, __float_as_uint(p)));
        p *= __fdividef(1.f, m);
        logC += __logf(m);
    }

#pragma unroll 1
    for (int o = 1; o < 64; o++) {
#pragma unroll
        for (int u = 0; u < 8; u++) e0[u] = e1[u];
        if (o < 63) {
            const int tn = (o + 1) * 8;
#pragma unroll
            for (int u = 0; u < 8; u++)
                e1[u] = act ? eb[(tn + u) * L_ + j] : 0.f;
        }
#pragma unroll
        for (int u = 0; u < 8; u++) { p = step2(p, w, offs, sp, buf, j, e0[u]); buf ^= 32; }
        float m = __uint_as_float(__reduce_max_sync(0xffffffffu, __float_as_uint(p)));
        p *= __fdividef(1.f, m);
        logC += __logf(m);
    }

    // target energy
    const size_t tb = (size_t)b * T_;
    float ts = 0.f;
    for (int t = j; t < T_; t += 32) {
        int tgt  = __ldg(&target32[(tb + t) * tstride]);
        int prev = (t == 0) ? IDX_BOS : __ldg(&target32[(tb + t - 1) * tstride]);
        tgt  = min(max(tgt,  0), L_ - 1);
        prev = min(max(prev, 0), L_ - 1);
        ts += __ldg(&trans[prev * L_ + tgt]) + __ldg(&g_outs[(tb + t) * L_ + tgt]);
    }
#pragma unroll
    for (int s = 16; s; s >>= 1) ts += __shfl_xor_sync(0xffffffffu, ts, s);

    float v = act ? __expf(__ldg(&trans[j * L_ + IDX_EOS])) * p : 0.f;
#pragma unroll
    for (int s = 16; s; s >>= 1) v += __shfl_xor_sync(0xffffffffu, v, s);

    if (j == 0) loss[b] = logC + __logf(v) - ts;
}

// ---------------------------------------------------------------------------
// Fused kernel: blocks [0,64) = per-batch scan (warp 0 only);
// blocks [64, 64+1024) = div-free energy write over 4-token groups.
// group g = tokens 4g..4g+3 : 961 float4s, 16B aligned.
// Per-thread slot pattern (trans value + outs offset) is group-invariant:
// precompute once, hot loop = 16 L1-hit LDG + 16 FADD + 4 STG.128.
// ---------------------------------------------------------------------------
#define SCANB 64
#define ENERB 1024
#define NGRP  (NTOK / 4)   // 8192 = 1024 * 8

__global__ __launch_bounds__(256) void fused_kernel(
    const float* __restrict__ trans,
    const int* __restrict__ target32,
    float* __restrict__ loss,
    float* __restrict__ energy)
{
    __shared__ float sp[64];

    if (blockIdx.x < SCANB) {
        if (threadIdx.x < 32)
            scan_body(blockIdx.x, threadIdx.x, trans, target32, loss, sp);
        return;
    }

    const int t = threadIdx.x;
    const bool has4 = (t <= 192);          // t+768 <= 960
    int vb0 = t, vb1 = t + 256, vb2 = t + 512, vb3 = t + 768;

    float tv[4][4];
    int   oo[4][4];
#pragma unroll
    for (int k = 0; k < 4; k++) {
        const int v = (k == 0) ? vb0 : (k == 1) ? vb1 : (k == 2) ? vb2 : vb3;
        if (k < 3 || has4) {
#pragma unroll
            for (int u = 0; u < 4; u++) {
                const int ff = 4 * v + u;          // 0..3843
                const int tg = ff / 961;
                const int r  = ff - tg * 961;
                oo[k][u] = tg * 31 + (r % 31);
                tv[k][u] = __ldg(&trans[r]);
            }
        }
    }

    float4* e4 = (float4*)energy;
    int g = blockIdx.x - SCANB;
#pragma unroll 1
    for (int it = 0; it < NGRP / ENERB; it++, g += ENERB) {
        const float* ob = g_outs + (size_t)g * 124;
        const size_t base = (size_t)g * 961;
        {
            float4 r4;
            r4.x = tv[0][0] + __ldg(&ob[oo[0][0]]);
            r4.y = tv[0][1] + __ldg(&ob[oo[0][1]]);
            r4.z = tv[0][2] + __ldg(&ob[oo[0][2]]);
            r4.w = tv[0][3] + __ldg(&ob[oo[0][3]]);
            e4[base + vb0] = r4;
        }
        {
            float4 r4;
            r4.x = tv[1][0] + __ldg(&ob[oo[1][0]]);
            r4.y = tv[1][1] + __ldg(&ob[oo[1][1]]);
            r4.z = tv[1][2] + __ldg(&ob[oo[1][2]]);
            r4.w = tv[1][3] + __ldg(&ob[oo[1][3]]);
            e4[base + vb1] = r4;
        }
        {
            float4 r4;
            r4.x = tv[2][0] + __ldg(&ob[oo[2][0]]);
            r4.y = tv[2][1] + __ldg(&ob[oo[2][1]]);
            r4.z = tv[2][2] + __ldg(&ob[oo[2][2]]);
            r4.w = tv[2][3] + __ldg(&ob[oo[2][3]]);
            e4[base + vb2] = r4;
        }
        if (has4) {
            float4 r4;
            r4.x = tv[3][0] + __ldg(&ob[oo[3][0]]);
            r4.y = tv[3][1] + __ldg(&ob[oo[3][1]]);
            r4.z = tv[3][2] + __ldg(&ob[oo[3][2]]);
            r4.w = tv[3][3] + __ldg(&ob[oo[3][3]]);
            e4[base + vb3] = r4;
        }
    }
}

// ---------------------------------------------------------------------------
extern "C" void kernel_launch(void* const* d_in, const int* in_sizes, int n_in,
                              void* d_out, int out_size)
{
    const float* input   = (const float*)d_in[0];
    const int*   target  = (const int*)d_in[1];   // int32 or int64 (auto-detected)
    const float* mask    = (const float*)d_in[2];
    const float* state_w = (const float*)d_in[3];
    const float* state_b = (const float*)d_in[4];
    const float* trans   = (const float*)d_in[5];

    float* out    = (float*)d_out;
    float* loss   = out;            // 64 floats
    float* energy = out + B_;       // B*T*31*31 floats (offset 256B, 16B aligned)

    gemm_kernel<<<NTOK / 128, 128>>>(input, state_w, state_b, mask);
    fused_kernel<<<SCANB + ENERB, 256>>>(trans, target, loss, energy);
}

// round 9
// speedup vs baseline: 1.4768x; 1.0290x over previous
#include <cuda_runtime.h>
#include <cstdint>

// Shapes (fixed by the problem)
#define B_  64
#define T_  512
#define D_  768
#define L_  31
#define LL_ 961
#define NTOK (B_*T_)      // 32768
#define IDX_EOS 29
#define IDX_BOS 30

// Scratch (static __device__, no allocation)
__device__ float g_outs[NTOK * L_];   // out_s (post bias + mask adjust)
__device__ float g_eos [NTOK * L_];   // exp(out_s)
__device__ float g_whi [D_ * 32];     // tf32-hi of state_w, [k][label], label 31 = 0
__device__ float g_wlo [D_ * 32];     // tf32-lo residual

__device__ __forceinline__ float f2tf32(float x) {
    float r; asm("cvt.rna.tf32.f32 %0, %1;" : "=f"(r) : "f"(x)); return r;
}

__device__ __forceinline__ void mma8(float& c0, float& c1, float& c2, float& c3,
    unsigned a0, unsigned a1, unsigned a2, unsigned a3, unsigned b0, unsigned b1)
{
    asm("mma.sync.aligned.m16n8k8.row.col.f32.tf32.tf32.f32 "
        "{%0,%1,%2,%3}, {%4,%5,%6,%7}, {%8,%9}, {%0,%1,%2,%3};"
        : "+f"(c0), "+f"(c1), "+f"(c2), "+f"(c3)
        : "r"(a0), "r"(a1), "r"(a2), "r"(a3), "r"(b0), "r"(b1));
}

// ---------------------------------------------------------------------------
// Kernel 0: split weights into tf32 hi/lo, k-major padded to 32 labels.
// ---------------------------------------------------------------------------
__global__ __launch_bounds__(256) void prep_w(const float* __restrict__ w)
{
    int i = blockIdx.x * 256 + threadIdx.x;
    if (i >= D_ * 32) return;
    int k = i >> 5, j = i & 31;
    float v = (j < L_) ? __ldg(&w[j * D_ + k]) : 0.f;
    float hi = f2tf32(v);
    g_whi[i] = hi;
    g_wlo[i] = f2tf32(v - hi);
}

// ---------------------------------------------------------------------------
// Kernel 1: fused 3xTF32 GEMM + bias/mask + g_outs/g_eos + full energy write.
// Block: 128 threads (4 warps), tile 64 tokens x 32 labels, k-chunk 32.
// Warp w owns rows 16w..16w+15; 4 n8 tiles cover 32 labels; 3 mma passes
// (hi*hi, hi*lo, lo*hi) give ~2^-22 relative accuracy.
// Epilogue: outs tile -> smem -> g_outs/g_eos + energy[64 tok x 961] float4.
// ---------------------------------------------------------------------------
#define CH  32
#define NCH (D_/CH)   // 24

__global__ __launch_bounds__(128) void gemm_energy(
    const float* __restrict__ input,
    const float* __restrict__ state_b,
    const float* __restrict__ mask,
    const float* __restrict__ trans,
    float* __restrict__ energy)
{
    __shared__ __align__(16) float sA [2][64 * 36];   // [tok][32k], pitch 36
    __shared__ __align__(16) float sBh[2][32 * 40];   // [k][32n],  pitch 40
    __shared__ __align__(16) float sBl[2][32 * 40];
    __shared__ float strans[LL_];

    const int tid  = threadIdx.x;
    const int lane = tid & 31, warp = tid >> 5;
    const int tokbase = blockIdx.x * 64;

    for (int i = tid; i < LL_; i += 128) strans[i] = __ldg(&trans[i]);

    float c[4][4];
#pragma unroll
    for (int t4 = 0; t4 < 4; t4++)
#pragma unroll
        for (int u = 0; u < 4; u++) c[t4][u] = 0.f;

    float4 ra[4], rh[2], rl[2];

    auto loadg = [&](int k0) {
#pragma unroll
        for (int i = 0; i < 4; i++) {
            int idx = tid + 128 * i; int row = idx >> 3, c4 = idx & 7;
            ra[i] = *(const float4*)&input[(size_t)(tokbase + row) * D_ + k0 + c4 * 4];
        }
#pragma unroll
        for (int i = 0; i < 2; i++) {
            int idx = tid + 128 * i; int k = idx >> 3, n4 = idx & 7;
            rh[i] = *(const float4*)&g_whi[(k0 + k) * 32 + n4 * 4];
            rl[i] = *(const float4*)&g_wlo[(k0 + k) * 32 + n4 * 4];
        }
    };
    auto stores = [&](int b) {
#pragma unroll
        for (int i = 0; i < 4; i++) {
            int idx = tid + 128 * i; int row = idx >> 3, c4 = idx & 7;
            *(float4*)&sA[b][row * 36 + c4 * 4] = ra[i];
        }
#pragma unroll
        for (int i = 0; i < 2; i++) {
            int idx = tid + 128 * i; int k = idx >> 3, n4 = idx & 7;
            *(float4*)&sBh[b][k * 40 + n4 * 4] = rh[i];
            *(float4*)&sBl[b][k * 40 + n4 * 4] = rl[i];
        }
    };

    loadg(0); stores(0); __syncthreads();

    int buf = 0;
    for (int ch = 0; ch < NCH; ch++) {
        if (ch + 1 < NCH) loadg((ch + 1) * CH);

        const float* A  = sA [buf];
        const float* Bh = sBh[buf];
        const float* Bl = sBl[buf];

#pragma unroll
        for (int kk = 0; kk < CH; kk += 8) {
            const int ar = warp * 16 + (lane >> 2);
            const int ak = kk + (lane & 3);
            float a0f = A[ar * 36 + ak];
            float a1f = A[ar * 36 + ak + 4];
            float a2f = A[(ar + 8) * 36 + ak];
            float a3f = A[(ar + 8) * 36 + ak + 4];

            float h0 = f2tf32(a0f), h1 = f2tf32(a1f), h2 = f2tf32(a2f), h3 = f2tf32(a3f);
            unsigned ah0 = __float_as_uint(h0), ah1 = __float_as_uint(h1);
            unsigned ah2 = __float_as_uint(h2), ah3 = __float_as_uint(h3);
            unsigned al0 = __float_as_uint(f2tf32(a0f - h0));
            unsigned al1 = __float_as_uint(f2tf32(a1f - h1));
            unsigned al2 = __float_as_uint(f2tf32(a2f - h2));
            unsigned al3 = __float_as_uint(f2tf32(a3f - h3));

            const int bk = (kk + (lane & 3)) * 40 + (lane >> 2);
#pragma unroll
            for (int t4 = 0; t4 < 4; t4++) {
                unsigned bh0 = __float_as_uint(Bh[bk + t4 * 8]);
                unsigned bh1 = __float_as_uint(Bh[bk + 160 + t4 * 8]);  // +4 k rows
                unsigned bl0 = __float_as_uint(Bl[bk + t4 * 8]);
                unsigned bl1 = __float_as_uint(Bl[bk + 160 + t4 * 8]);
                mma8(c[t4][0], c[t4][1], c[t4][2], c[t4][3], ah0, ah1, ah2, ah3, bh0, bh1);
                mma8(c[t4][0], c[t4][1], c[t4][2], c[t4][3], ah0, ah1, ah2, ah3, bl0, bl1);
                mma8(c[t4][0], c[t4][1], c[t4][2], c[t4][3], al0, al1, al2, al3, bh0, bh1);
            }
        }
        __syncthreads();
        if (ch + 1 < NCH) { stores(buf ^ 1); __syncthreads(); }
        buf ^= 1;
    }

    // ---- epilogue: outs tile to smem (overlay on sA, dead now) ----
    float* outs = sA[0];                     // 64 x 32, pitch 32
    {
        const int r0 = warp * 16 + (lane >> 2);
        const int jb = 2 * (lane & 3);
        const float mk0 = __ldg(&mask[tokbase + r0]);
        const float mk1 = __ldg(&mask[tokbase + r0 + 8]);
#pragma unroll
        for (int t4 = 0; t4 < 4; t4++) {
            const int j0 = t4 * 8 + jb;
            float bb = __ldg(&state_b[j0]);
            float v00 = c[t4][0] + bb, v10 = c[t4][2] + bb;
            if (j0 == IDX_EOS) { v00 += (mk0 == 0.f) ? 2e4f : 0.f;
                                 v10 += (mk1 == 0.f) ? 2e4f : 0.f; }
            outs[r0 * 32 + j0]       = v00;
            outs[(r0 + 8) * 32 + j0] = v10;
            const int j1 = j0 + 1;
            if (j1 < L_) {
                float bb1 = __ldg(&state_b[j1]);
                float v01 = c[t4][1] + bb1, v11 = c[t4][3] + bb1;
                if (j1 == IDX_EOS) { v01 += (mk0 == 0.f) ? 2e4f : 0.f;
                                     v11 += (mk1 == 0.f) ? 2e4f : 0.f; }
                outs[r0 * 32 + j1]       = v01;
                outs[(r0 + 8) * 32 + j1] = v11;
            }
        }
    }
    __syncthreads();

    // ---- g_outs / g_eos ----
    for (int i = tid; i < 64 * L_; i += 128) {
        int tok = i / L_;
        int j   = i - tok * L_;
        float v = outs[tok * 32 + j];
        size_t gi = (size_t)(tokbase + tok) * L_ + j;
        g_outs[gi] = v;
        g_eos [gi] = __expf(v);
    }

    // ---- energy: 16 groups of 4 tokens, 961 float4 per group ----
    int pko[8], pr0[8];
#pragma unroll
    for (int s = 0; s < 8; s++) {
        int v  = tid + 128 * s;
        int ff = 4 * v;
        int t0 = ff / 961;
        pr0[s] = ff - t0 * 961;
        int oj = 0;
#pragma unroll
        for (int u = 0; u < 4; u++) {
            int fu = ff + u;
            int tl = fu / 961;
            int r  = fu - tl * 961;
            int j  = r % 31;
            oj |= ((tl * 32 + j) & 255) << (8 * u);
        }
        pko[s] = oj;
    }

    float4* e4 = (float4*)energy;
#pragma unroll 1
    for (int g2 = 0; g2 < 16; g2++) {
        const float* ob = outs + g2 * 128;                       // 4 tokens * 32
        const size_t base4 = ((size_t)(tokbase + 4 * g2) * 961) >> 2;
#pragma unroll
        for (int s = 0; s < 8; s++) {
            int v = tid + 128 * s;
            if (v <= 960) {
                int r = pr0[s], oj = pko[s];
                float4 o;
                o.x = strans[r] + ob[oj & 127];
                int r1 = r + 1; if (r1 >= 961) r1 -= 961;
                o.y = strans[r1] + ob[(oj >> 8) & 127];
                int r2 = r + 2; if (r2 >= 961) r2 -= 961;
                o.z = strans[r2] + ob[(oj >> 16) & 127];
                int r3 = r + 3; if (r3 >= 961) r3 -= 961;
                o.w = strans[r3] + ob[(oj >> 24) & 127];
                e4[base4 + v] = o;
            }
        }
    }
}

// ---------------------------------------------------------------------------
// Kernel 2: linear-space forward scan, sparse gathers via 16 shfl.idx
// (per-lane variable sources), no syncwarp, no smem. One warp per batch.
// ---------------------------------------------------------------------------
__device__ __forceinline__ float stepS(float p, const float (&w)[16],
                                       const int (&sc)[16], float e)
{
    float a0 = 0.f, a1 = 0.f, a2 = 0.f, a3 = 0.f;
#pragma unroll
    for (int k = 0; k < 16; k += 4) {
        a0 = fmaf(w[k],   __shfl_sync(0xffffffffu, p, sc[k]),   a0);
        a1 = fmaf(w[k+1], __shfl_sync(0xffffffffu, p, sc[k+1]), a1);
        a2 = fmaf(w[k+2], __shfl_sync(0xffffffffu, p, sc[k+2]), a2);
        a3 = fmaf(w[k+3], __shfl_sync(0xffffffffu, p, sc[k+3]), a3);
    }
    return ((a0 + a1) + (a2 + a3)) * e;
}

__global__ __launch_bounds__(32) void scan_kernel(
    const float* __restrict__ trans,
    const int* __restrict__ target32,
    float* __restrict__ loss)
{
    const int b = blockIdx.x;
    const int j = threadIdx.x;
    const bool act = (j < L_);
    const float* eb = g_eos + (size_t)b * T_ * L_;

    // dtype detection: int64 target (LE) has zero high words at odd positions
    bool is64 = true;
#pragma unroll
    for (int q = 0; q < 64; q++) is64 &= (__ldg(&target32[2 * q + 1]) == 0);
    const int tstride = is64 ? 2 : 1;

    // per-lane sources: heavy cols gather row pairs {2,3},{6,7},...,{26,27},{28,29};
    // light cols (is_/es) gather their single pair {4m,4m+1} (rest get w=0).
    const bool light = (j < 28) && (((j & 3) == 1) || ((j & 3) == 2));
    int sc[16];
    const int base0 = light ? (j & ~3) : 2;
    sc[0] = base0; sc[1] = base0 + 1;
#pragma unroll
    for (int k = 1; k < 7; k++) { sc[2*k] = 4*k + 2; sc[2*k+1] = 4*k + 3; }
    sc[14] = 28; sc[15] = 29;

    float w[16];
#pragma unroll
    for (int k = 0; k < 16; k++)
        w[k] = act ? __expf(__ldg(&trans[sc[k] * L_ + j])) : 0.f;

    float p = act ? __expf(__ldg(&trans[IDX_BOS * L_ + j])) * __ldg(&eb[j]) : 0.f;
    float logC = 0.f;

    float e0[8], e1[8];
#pragma unroll
    for (int u = 0; u < 7; u++) e0[u] = act ? eb[(1 + u) * L_ + j] : 0.f;
#pragma unroll
    for (int u = 0; u < 8; u++) e1[u] = act ? eb[(8 + u) * L_ + j] : 0.f;

#pragma unroll
    for (int u = 0; u < 7; u++) p = stepS(p, w, sc, e0[u]);
    {
        float m = __uint_as_float(__reduce_max_sync(0xffffffffu, __float_as_uint(p)));
        p *= __fdividef(1.f, m);
        logC += __logf(m);
    }

#pragma unroll 1
    for (int o = 1; o < 64; o++) {
#pragma unroll
        for (int u = 0; u < 8; u++) e0[u] = e1[u];
        if (o < 63) {
            const int tn = (o + 1) * 8;
#pragma unroll
            for (int u = 0; u < 8; u++)
                e1[u] = act ? eb[(tn + u) * L_ + j] : 0.f;
        }
#pragma unroll
        for (int u = 0; u < 8; u++) p = stepS(p, w, sc, e0[u]);
        float m = __uint_as_float(__reduce_max_sync(0xffffffffu, __float_as_uint(p)));
        p *= __fdividef(1.f, m);
        logC += __logf(m);
    }

    // target energy
    const size_t tb = (size_t)b * T_;
    float ts = 0.f;
    for (int t = j; t < T_; t += 32) {
        int tgt  = __ldg(&target32[(tb + t) * tstride]);
        int prev = (t == 0) ? IDX_BOS : __ldg(&target32[(tb + t - 1) * tstride]);
        tgt  = min(max(tgt,  0), L_ - 1);
        prev = min(max(prev, 0), L_ - 1);
        ts += __ldg(&trans[prev * L_ + tgt]) + __ldg(&g_outs[(tb + t) * L_ + tgt]);
    }
#pragma unroll
    for (int s = 16; s; s >>= 1) ts += __shfl_xor_sync(0xffffffffu, ts, s);

    float v = act ? __expf(__ldg(&trans[j * L_ + IDX_EOS])) * p : 0.f;
#pragma unroll
    for (int s = 16; s; s >>= 1) v += __shfl_xor_sync(0xffffffffu, v, s);

    if (j == 0) loss[b] = logC + __logf(v) - ts;
}

// ---------------------------------------------------------------------------
extern "C" void kernel_launch(void* const* d_in, const int* in_sizes, int n_in,
                              void* d_out, int out_size)
{
    const float* input   = (const float*)d_in[0];
    const int*   target  = (const int*)d_in[1];   // int32 or int64 (auto-detected)
    const float* mask    = (const float*)d_in[2];
    const float* state_w = (const float*)d_in[3];
    const float* state_b = (const float*)d_in[4];
    const float* trans   = (const float*)d_in[5];

    float* out    = (float*)d_out;
    float* loss   = out;            // 64 floats
    float* energy = out + B_;       // B*T*31*31 floats (offset 256B, 16B aligned)

    prep_w<<<(D_ * 32 + 255) / 256, 256>>>(state_w);
    gemm_energy<<<NTOK / 64, 128>>>(input, state_b, mask, trans, energy);
    scan_kernel<<<B_, 32>>>(trans, target, loss);
}